// round 1
// baseline (speedup 1.0000x reference)
#include <cuda_runtime.h>

#define BB 32
#define LL 64
#define CC 4
#define NPAIRS 2016        // L*(L-1)/2
#define NCHUNK 8           // pair-chunks per batch
#define WPB 8              // warps per block

// scratch: per-(batch, position) flattened one-hot offset o = l*C + c
__device__ int g_off[BB * LL];

// Kernel 1: compute offsets, write out[b] = theta0 + sum_l theta1[o_l]
__global__ void init_kernel(const float* __restrict__ x,
                            const float* __restrict__ th0,
                            const float* __restrict__ th1,
                            float* __restrict__ out) {
    int b = blockIdx.x;
    int l = threadIdx.x;
    const float* xb = x + b * (LL * CC) + l * CC;
    int c = 0;
    if (xb[1] > 0.5f) c = 1;
    else if (xb[2] > 0.5f) c = 2;
    else if (xb[3] > 0.5f) c = 3;
    int o = l * CC + c;
    g_off[b * LL + l] = o;

    __shared__ float s[LL];
    s[l] = th1[o];
    __syncthreads();
    #pragma unroll
    for (int stride = LL / 2; stride > 0; stride >>= 1) {
        if (l < stride) s[l] += s[l + stride];
        __syncthreads();
    }
    if (l == 0) out[b] = th0[0] + s[0];
}

// Kernel 2: order-2 + order-3 gathers over strict triangles, atomicAdd into out
__global__ void pair_kernel(const float* __restrict__ th2,
                            const float* __restrict__ th3,
                            float* __restrict__ out) {
    int b = blockIdx.x / NCHUNK;
    int chunk = blockIdx.x % NCHUNK;
    int tid = threadIdx.x;

    __shared__ int so[LL];
    if (tid < LL) so[tid] = g_off[b * LL + tid];
    __syncthreads();

    int warp = tid >> 5, lane = tid & 31;
    int wg = chunk * WPB + warp;          // global warp-group id in [0, NCHUNK*WPB)

    float acc = 0.f;
    for (int p = wg; p < NPAIRS; p += NCHUNK * WPB) {
        // decode strict-lower-triangle pair: p = l1*(l1-1)/2 + l0, l0 < l1
        int l1 = (int)((1.0f + sqrtf(8.0f * (float)p + 1.0f)) * 0.5f);
        while (l1 * (l1 - 1) / 2 > p) l1--;
        while ((l1 + 1) * l1 / 2 <= p) l1++;
        int l0 = p - l1 * (l1 - 1) / 2;

        int base2 = so[l0] * 256 + so[l1];
        if (lane == 0) acc += th2[base2];

        const float* __restrict__ row = th3 + (size_t)base2 * 256;
        for (int l2 = l1 + 1 + lane; l2 < LL; l2 += 32)
            acc += row[so[l2]];
    }

    // block reduction
    #pragma unroll
    for (int off = 16; off > 0; off >>= 1)
        acc += __shfl_down_sync(0xffffffffu, acc, off);
    __shared__ float ws[WPB];
    if (lane == 0) ws[warp] = acc;
    __syncthreads();
    if (tid == 0) {
        float t = 0.f;
        #pragma unroll
        for (int w = 0; w < WPB; w++) t += ws[w];
        atomicAdd(&out[b], t);
    }
}

extern "C" void kernel_launch(void* const* d_in, const int* in_sizes, int n_in,
                              void* d_out, int out_size) {
    const float* x   = (const float*)d_in[0];   // (B, L*C) one-hot
    const float* th0 = (const float*)d_in[1];   // (1,)
    const float* th1 = (const float*)d_in[2];   // (L, C)
    const float* th2 = (const float*)d_in[3];   // (L, C, L, C)
    const float* th3 = (const float*)d_in[4];   // (L, C, L, C, L, C)
    float* out = (float*)d_out;                 // (B, 1)

    init_kernel<<<BB, LL>>>(x, th0, th1, out);
    pair_kernel<<<BB * NCHUNK, WPB * 32>>>(th2, th3, out);
}

// round 2
// speedup vs baseline: 2.4270x; 2.4270x over previous
#include <cuda_runtime.h>

#define BB 32
#define LL 64
#define CC 4
#define NPAIRS 2016          // L*(L-1)/2
#define CHUNKS 32            // blocks per batch
#define PAIRS_PER_BLOCK 64   // 256 threads / 4 lanes-per-pair

// One kernel: order 0+1 (chunk-0 blocks) + order 2+3 (all blocks).
// out must be zeroed beforehand (cudaMemsetAsync in kernel_launch).
__global__ void __launch_bounds__(256) gp_kernel(
        const float* __restrict__ x,
        const float* __restrict__ th0,
        const float* __restrict__ th1,
        const float* __restrict__ th2,
        const float* __restrict__ th3,
        float* __restrict__ out) {
    const int b     = blockIdx.x >> 5;       // / CHUNKS
    const int chunk = blockIdx.x & 31;       // % CHUNKS
    const int tid   = threadIdx.x;
    const int sub   = tid & 3;               // lane within pair-group
    const int p     = chunk * PAIRS_PER_BLOCK + (tid >> 2);

    __shared__ float4 sx[LL];     // x_b as float4 per position
    __shared__ int    so[LL];     // flattened one-hot offsets o = l*4+c
    __shared__ float  wsum[8];

    if (tid < LL) {
        float4 v = ((const float4*)x)[b * LL + tid];
        sx[tid] = v;
        int c = v.y > 0.5f ? 1 : (v.z > 0.5f ? 2 : (v.w > 0.5f ? 3 : 0));
        so[tid] = tid * CC + c;
    }
    __syncthreads();

    float acc = 0.f;

    if (p < NPAIRS) {
        // branchless decode: p = l1*(l1-1)/2 + l0, l0 < l1
        int l1 = (int)((1.0f + sqrtf(8.0f * (float)p + 1.0f)) * 0.5f);
        if ((l1 * (l1 - 1)) >> 1 > p) l1--;
        if (((l1 + 1) * l1) >> 1 <= p) l1++;
        const int l0 = p - ((l1 * (l1 - 1)) >> 1);

        const int base2 = so[l0] * 256 + so[l1];
        const float4* __restrict__ row4 = (const float4*)th3 + (size_t)base2 * 64;

        #pragma unroll 4
        for (int l2 = l1 + 1 + sub; l2 < LL; l2 += 4) {
            float4 r  = row4[l2];
            float4 xv = sx[l2];
            acc = fmaf(r.x, xv.x, acc);
            acc = fmaf(r.y, xv.y, acc);
            acc = fmaf(r.z, xv.z, acc);
            acc = fmaf(r.w, xv.w, acc);
        }
        if (sub == 0) acc += th2[base2];     // order-2 term for this pair
    }

    // order 0 + 1, folded into chunk-0 blocks (first 64 threads)
    if (chunk == 0 && tid < LL) {
        acc += th1[so[tid]];
        if (tid == 0) acc += th0[0];
    }

    // full-warp butterfly (all pairs in warp share batch b)
    #pragma unroll
    for (int off = 16; off > 0; off >>= 1)
        acc += __shfl_xor_sync(0xffffffffu, acc, off);

    const int warp = tid >> 5;
    if ((tid & 31) == 0) wsum[warp] = acc;
    __syncthreads();
    if (tid == 0) {
        float t = 0.f;
        #pragma unroll
        for (int w = 0; w < 8; w++) t += wsum[w];
        atomicAdd(&out[b], t);
    }
}

extern "C" void kernel_launch(void* const* d_in, const int* in_sizes, int n_in,
                              void* d_out, int out_size) {
    const float* x   = (const float*)d_in[0];   // (B, L*C) one-hot
    const float* th0 = (const float*)d_in[1];   // (1,)
    const float* th1 = (const float*)d_in[2];   // (L, C)
    const float* th2 = (const float*)d_in[3];   // (L*C, L*C)
    const float* th3 = (const float*)d_in[4];   // (L*C, L*C, L*C)
    float* out = (float*)d_out;                 // (B, 1)

    cudaMemsetAsync(out, 0, (size_t)out_size * sizeof(float));
    gp_kernel<<<BB * CHUNKS, 256>>>(x, th0, th1, th2, th3, out);
}